// round 17
// baseline (speedup 1.0000x reference)
#include <cuda_runtime.h>
#include <stdint.h>

// ---------------------------------------------------------------------------
// CoralLoss single-kernel: mean over (B, K-1) of softplus(s),
//   s = (target > k) ? -x : x
// loss_elem = 0.5*|x| + g*x + ln(1+u),  g = +-0.5,  u = 2^(-|x|*log2e)
// R16: HALF-ROW mapping — kernel is memory-LATENCY bound (two instruction
// diets changed issue% but not duration; DRAM stuck at 59%). Each thread now
// front-batches 8 LDG.128 (32 elements = half a row) + 1 target word per
// iteration: ~2x bytes in flight per warp (Little's law shortfall was ~3x),
// half the target loads. Logits via __ldcg (L2-only; L1 had 0 reuse).
// deg-3 Chebyshev ln(1+u) (mean-level err ~1e-5 measured), C0 analytic.
// ---------------------------------------------------------------------------

#define NBLK 1184
#define NTHR 256
#define GS   (NBLK * NTHR)          // grid stride in chunks (even)

__device__ float    g_partial[NBLK];
__device__ unsigned g_count = 0;

__device__ __forceinline__ float ex2f(float x) {
    float r; asm("ex2.approx.f32 %0,%1;" : "=f"(r) : "f"(x)); return r;
}

// One element: accL += u*P(u); accH += 0.5|x|; accS += g*x.
// ln(1+u) = C0 + u*P(u); C0 = 5.043e-4 added analytically to the mean.
__device__ __forceinline__ void sp1(float x, float g,
                                    float& accL, float& accH, float& accS) {
    float u = ex2f(-1.4426950408889634f * fabsf(x));   // FMUL(|op|,imm)+MUFU
    float l = fmaf(u, 0.1077411f, -0.3971037f);        // deg-3 Chebyshev
    l = fmaf(u, l, 0.9823874f);
    accL = fmaf(u, l, accL);                           // += u*P(u)
    accH = fmaf(fabsf(x), 0.5f, accH);                 // |x| folds as modifier
    accS = fmaf(x, g, accS);
}

// One float4 at element offset TH within the half-row; flip comp c iff dd>TH+c.
template <int TH>
__device__ __forceinline__ void do4(float4 v, int dd,
                                    float& L0, float& L1, float& H0, float& H1,
                                    float& S0, float& S1) {
    sp1(v.x, (dd > TH + 0) ? -0.5f : 0.5f, L0, H0, S0);
    sp1(v.y, (dd > TH + 1) ? -0.5f : 0.5f, L1, H1, S1);
    sp1(v.z, (dd > TH + 2) ? -0.5f : 0.5f, L0, H0, S0);
    sp1(v.w, (dd > TH + 3) ? -0.5f : 0.5f, L1, H1, S1);
}

__global__ void __launch_bounds__(NTHR) coral_fused(
    const float4* __restrict__ lg,     // logits as float4, B*16 entries
    const int*    __restrict__ t32,    // targets viewed as int32 words
    int nchunk,                        // B*2 (chunks of 8 float4s = 32 elems)
    float* __restrict__ out,
    double inv_n)
{
    // ---- in-block dtype detection: int64 iff sampled odd words all zero ----
    __shared__ int s_is64;
    if (threadIdx.x < 32) {
        int nz = t32[2 * threadIdx.x + 1] | t32[2 * threadIdx.x + 65];
        unsigned m = __ballot_sync(0xFFFFFFFFu, nz != 0);
        if (threadIdx.x == 0) s_is64 = (m == 0);
    }
    __syncthreads();
    const int tsh = s_is64 ? 1 : 0;    // word-index shift (x2 for int64)

    const int c0   = blockIdx.x * NTHR + threadIdx.x;   // first chunk
    const int qoff = (c0 & 1) << 5;    // element offset of half-row in row
                                       // (invariant: GS even)
    const float4* p = lg + (size_t)c0 * 8;
    const int*    q = t32 + ((size_t)(c0 >> 1) << tsh);
    const size_t  pstep = (size_t)GS * 8;               // float4s per iter
    const size_t  qstep = (size_t)(GS >> 1) << tsh;     // target words per iter

    float L0 = 0.f, L1 = 0.f, H0 = 0.f, H1 = 0.f, S0 = 0.f, S1 = 0.f;

    for (int c = c0; c < nchunk; c += GS) {
        int tgt = *q;
        int dd  = tgt - qoff;          // flip element e of half-row iff dd > e

        // 8 front-batched L2-only loads: ~2x bytes in flight per warp
        float4 v0 = __ldcg(p + 0);
        float4 v1 = __ldcg(p + 1);
        float4 v2 = __ldcg(p + 2);
        float4 v3 = __ldcg(p + 3);
        float4 v4 = __ldcg(p + 4);
        float4 v5 = __ldcg(p + 5);
        float4 v6 = __ldcg(p + 6);
        float4 v7 = __ldcg(p + 7);

        do4<0 >(v0, dd, L0, L1, H0, H1, S0, S1);
        do4<4 >(v1, dd, L0, L1, H0, H1, S0, S1);
        do4<8 >(v2, dd, L0, L1, H0, H1, S0, S1);
        do4<12>(v3, dd, L0, L1, H0, H1, S0, S1);
        do4<16>(v4, dd, L0, L1, H0, H1, S0, S1);
        do4<20>(v5, dd, L0, L1, H0, H1, S0, S1);
        do4<24>(v6, dd, L0, L1, H0, H1, S0, S1);
        do4<28>(v7, dd, L0, L1, H0, H1, S0, S1);

        p += pstep;
        q += qstep;
    }

    // ---- per-thread combine ----
    float acc = (L0 + L1) + (H0 + H1) + (S0 + S1);

    // ---- block reduce ----
    #pragma unroll
    for (int o = 16; o > 0; o >>= 1)
        acc += __shfl_xor_sync(0xFFFFFFFFu, acc, o);

    __shared__ float sw[NTHR / 32];
    __shared__ bool amLast;
    int lane = threadIdx.x & 31;
    int warp = threadIdx.x >> 5;
    if (lane == 0) sw[warp] = acc;
    __syncthreads();

    if (threadIdx.x == 0) {
        float b = 0.0f;
        #pragma unroll
        for (int w = 0; w < NTHR / 32; w++) b += sw[w];
        g_partial[blockIdx.x] = b;
        __threadfence();
        unsigned t = atomicAdd(&g_count, 1u);
        amLast = (t == (unsigned)(gridDim.x - 1));
    }
    __syncthreads();

    // ---- last block: deterministic final reduce in double ----
    if (amLast) {
        __threadfence();
        double a = 0.0;
        for (int i = threadIdx.x; i < NBLK; i += NTHR)
            a += (double)g_partial[i];
        #pragma unroll
        for (int o = 16; o > 0; o >>= 1)
            a += __shfl_xor_sync(0xFFFFFFFFu, a, o);
        __shared__ double sd[NTHR / 32];
        if (lane == 0) sd[warp] = a;
        __syncthreads();
        if (threadIdx.x == 0) {
            double s = 0.0;
            #pragma unroll
            for (int w = 0; w < NTHR / 32; w++) s += sd[w];
            // + C0 (constant term of deg-3 ln(1+u) fit), applied analytically
            out[0] = (float)(s * inv_n + 5.043e-4);
            g_count = 0;   // reset for next graph replay
        }
    }
}

extern "C" void kernel_launch(void* const* d_in, const int* in_sizes, int n_in,
                              void* d_out, int out_size) {
    const float* logits = (const float*)d_in[0];
    const int*   t32    = (const int*)d_in[1];   // int32 view of targets
    int nelem  = in_sizes[0];                    // B * (K-1)
    int nchunk = nelem >> 5;                     // 32 elements per chunk

    coral_fused<<<NBLK, NTHR>>>((const float4*)logits, t32, nchunk,
                                (float*)d_out, 1.0 / (double)nelem);
}